// round 13
// baseline (speedup 1.0000x reference)
#include <cuda_runtime.h>
#include <cuda_fp16.h>
#include <cstdint>

// GraphAttentionLayer B=8,T=2048,D=256 — separable-softmax O(T*D) pipeline.
//  k1:       h = x@W^T (split-3 fp16 mma), s1/s2, h fp32
//  k_rank:   rank-by-counting sort of s2 (desc), split-count, scatter
//  k_prep:   fused per-batch scans (dp/dn in smem) + per-row binsearch coefs
//  k_scanloc:per-32-segment SINGLE-PASS prefixes of ep*h (P) and en*h (Q)
//  k_segscan:segment-total offsets (prefix for both P and Q)
//  k_out:    one block per row: p=P[k], n=Qtot−Q[k], combine, ELU

#define B_ 8
#define T_ 2048
#define NEG_SLOPE 0.2f

__device__ float g_hf[B_ * T_ * 256];
__device__ float g_s1[B_ * T_];
__device__ float g_s2[B_ * T_];
__device__ float g_s2s[B_ * T_];
__device__ int   g_perm[B_ * T_];
__device__ float g_ep[B_ * T_];
__device__ float g_en[B_ * T_];
__device__ int   g_kk[B_ * T_];
__device__ float g_cu[B_ * T_];
__device__ float g_cn[B_ * T_];
__device__ float g_Pl[B_ * 2049 * 256];
__device__ float g_Ql[B_ * 2049 * 256];
__device__ float g_segP[B_ * 64 * 256];
__device__ float g_segQ[B_ * 64 * 256];
__device__ float g_offP[B_ * 65 * 256];
__device__ float g_offQ[B_ * 65 * 256];

// ---------------- helpers ----------------------------------------------------
__device__ __forceinline__ uint32_t smem_u32(const void* p) {
  uint32_t a;
  asm("{ .reg .u64 t; cvta.to.shared.u64 t, %1; cvt.u32.u64 %0, t; }"
      : "=r"(a) : "l"(p));
  return a;
}
__device__ __forceinline__ void ldsm4(uint32_t addr, uint32_t r[4]) {
  asm volatile("ldmatrix.sync.aligned.m8n8.x4.shared.b16 {%0,%1,%2,%3}, [%4];"
               : "=r"(r[0]), "=r"(r[1]), "=r"(r[2]), "=r"(r[3]) : "r"(addr));
}
__device__ __forceinline__ void mma16816(float c[4], const uint32_t a[4],
                                         uint32_t b0, uint32_t b1) {
  asm volatile(
      "mma.sync.aligned.m16n8k16.row.col.f32.f16.f16.f32 "
      "{%0,%1,%2,%3}, {%4,%5,%6,%7}, {%8,%9}, {%0,%1,%2,%3};"
      : "+f"(c[0]), "+f"(c[1]), "+f"(c[2]), "+f"(c[3])
      : "r"(a[0]), "r"(a[1]), "r"(a[2]), "r"(a[3]), "r"(b0), "r"(b1));
}
__device__ __forceinline__ void cpa16(uint32_t dst, const void* src) {
  asm volatile("cp.async.cg.shared.global [%0], [%1], 16;" :: "r"(dst), "l"(src)
               : "memory");
}
#define CP_COMMIT() asm volatile("cp.async.commit_group;" ::: "memory")
#define CP_WAIT(n) asm volatile("cp.async.wait_group %0;" :: "n"(n) : "memory")

__device__ __forceinline__ void split8(const float* v, uint4& hi, uint4& lo) {
  uint32_t h[4], l[4];
#pragma unroll
  for (int q = 0; q < 4; q++) {
    float a = v[2 * q], b = v[2 * q + 1];
    __half ah = __float2half_rn(a), bh = __float2half_rn(b);
    __half2 hv; hv.x = ah; hv.y = bh; h[q] = *(uint32_t*)&hv;
    __half2 lv;
    lv.x = __float2half_rn(a - __half2float(ah));
    lv.y = __float2half_rn(b - __half2float(bh));
    l[q] = *(uint32_t*)&lv;
  }
  hi = make_uint4(h[0], h[1], h[2], h[3]);
  lo = make_uint4(l[0], l[1], l[2], l[3]);
}

// ============================================================================
// K1: h = x @ W^T (split-3 fp16 mma), epilogue: s1/s2 + h fp32 store.
// ============================================================================
#define K1_FX 0
#define K1_FW 34816
#define K1_AH 104448
#define K1_AL 122880
#define K1_BH 141312
#define K1_BL 178176
#define K1_AS 215040
#define K1_R1 217088
#define K1_R2 219136
#define K1_SMEM 221184

__global__ __launch_bounds__(512, 1) void k1(
    const float* __restrict__ x, const float* __restrict__ W,
    const float* __restrict__ a) {
  extern __shared__ char sm[];
  const uint32_t SB = smem_u32(sm);
  const int t = threadIdx.x, lane = t & 31, wid = t >> 5;
  const int warpM = wid >> 2, warpN = wid & 3;
  const int i0 = blockIdx.x * 128;

#define K1_LOADF32(cc) do {                                                   \
    const int k0_ = (cc) * 64;                                                \
    _Pragma("unroll")                                                         \
    for (int v = 0; v < 4; v++) {                                             \
      int u = v * 512 + t, row = u >> 4, seg = u & 15;                        \
      cpa16(SB + K1_FX + (uint32_t)(row * 68 + seg * 4) * 4,                  \
            &x[(size_t)(i0 + row) * 256 + k0_ + seg * 4]);                    \
    }                                                                         \
    _Pragma("unroll")                                                         \
    for (int v = 0; v < 8; v++) {                                             \
      int u = v * 512 + t, row = u >> 4, seg = u & 15;                        \
      cpa16(SB + K1_FW + (uint32_t)(row * 68 + seg * 4) * 4,                  \
            &W[(size_t)row * 256 + k0_ + seg * 4]);                           \
    }                                                                         \
  } while (0)

  K1_LOADF32(0);
  CP_COMMIT();
  ((float*)(sm + K1_AS))[t] = a[t];

  float c[2][8][4];
#pragma unroll
  for (int r = 0; r < 2; r++)
#pragma unroll
    for (int f = 0; f < 8; f++)
#pragma unroll
      for (int q = 0; q < 4; q++) c[r][f][q] = 0.f;

  CP_WAIT(0);
  __syncthreads();

  for (int ch = 0; ch < 4; ch++) {
    {
      const int row = t >> 2, quad = t & 3;
      float v[16];
#pragma unroll
      for (int q = 0; q < 4; q++)
        *(float4*)&v[q * 4] =
            *(const float4*)(sm + K1_FX + (uint32_t)(row * 68 + quad * 16 + q * 4) * 4);
      uint4 h0, l0, h1, l1;
      split8(v, h0, l0); split8(v + 8, h1, l1);
      const uint32_t off = (uint32_t)(row * 72 + quad * 16) * 2;
      *(uint4*)(sm + K1_AH + off) = h0; *(uint4*)(sm + K1_AH + off + 16) = h1;
      *(uint4*)(sm + K1_AL + off) = l0; *(uint4*)(sm + K1_AL + off + 16) = l1;
    }
    {
      const int row = t >> 1, half = (t & 1) * 32;
      float v[32];
#pragma unroll
      for (int q = 0; q < 8; q++)
        *(float4*)&v[q * 4] =
            *(const float4*)(sm + K1_FW + (uint32_t)(row * 68 + half + q * 4) * 4);
      const uint32_t off = (uint32_t)(row * 72 + half) * 2;
#pragma unroll
      for (int g = 0; g < 4; g++) {
        uint4 hh, ll;
        split8(v + g * 8, hh, ll);
        *(uint4*)(sm + K1_BH + off + g * 16) = hh;
        *(uint4*)(sm + K1_BL + off + g * 16) = ll;
      }
    }
    __syncthreads();
    if (ch < 3) { K1_LOADF32(ch + 1); CP_COMMIT(); }

#pragma unroll
    for (int ks = 0; ks < 64; ks += 16) {
      const uint32_t lrow = (uint32_t)(lane & 15);
      const uint32_t lcol = (uint32_t)(ks + ((lane >> 4) << 3));
      uint32_t ah[2][4], al[2][4];
#pragma unroll
      for (int r = 0; r < 2; r++) {
        uint32_t ra = SB + ((warpM * 32 + r * 16 + lrow) * 72 + lcol) * 2;
        ldsm4(ra + K1_AH, ah[r]);
        ldsm4(ra + K1_AL, al[r]);
      }
      uint32_t bh[8][2], bl[8][2];
#pragma unroll
      for (int q = 0; q < 4; q++) {
        uint32_t rb = SB + ((warpN * 64 + q * 16 + lrow) * 72 + lcol) * 2;
        uint32_t rr[4];
        ldsm4(rb + K1_BH, rr);
        bh[2 * q][0] = rr[0]; bh[2 * q + 1][0] = rr[1];
        bh[2 * q][1] = rr[2]; bh[2 * q + 1][1] = rr[3];
        ldsm4(rb + K1_BL, rr);
        bl[2 * q][0] = rr[0]; bl[2 * q + 1][0] = rr[1];
        bl[2 * q][1] = rr[2]; bl[2 * q + 1][1] = rr[3];
      }
#pragma unroll
      for (int r = 0; r < 2; r++)
#pragma unroll
        for (int f = 0; f < 8; f++) mma16816(c[r][f], ah[r], bh[f][0], bh[f][1]);
#pragma unroll
      for (int r = 0; r < 2; r++)
#pragma unroll
        for (int f = 0; f < 8; f++) mma16816(c[r][f], ah[r], bl[f][0], bl[f][1]);
#pragma unroll
      for (int r = 0; r < 2; r++)
#pragma unroll
        for (int f = 0; f < 8; f++) mma16816(c[r][f], al[r], bh[f][0], bh[f][1]);
    }
    CP_WAIT(0);
    __syncthreads();
  }

  const float* as_ = (const float*)(sm + K1_AS);
  float s1p[4], s2p[4];
#pragma unroll
  for (int q = 0; q < 4; q++) { s1p[q] = 0.f; s2p[q] = 0.f; }
#pragma unroll
  for (int r = 0; r < 2; r++)
#pragma unroll
    for (int f = 0; f < 8; f++)
#pragma unroll
      for (int q = 0; q < 4; q++) {
        int col = warpN * 64 + f * 8 + 2 * (lane & 3) + (q & 1);
        int ri = r * 2 + (q >> 1);
        s1p[ri] += c[r][f][q] * as_[col];
        s2p[ri] += c[r][f][q] * as_[256 + col];
      }
#pragma unroll
  for (int o = 1; o < 4; o <<= 1)
#pragma unroll
    for (int ri = 0; ri < 4; ri++) {
      s1p[ri] += __shfl_xor_sync(0xffffffffu, s1p[ri], o);
      s2p[ri] += __shfl_xor_sync(0xffffffffu, s2p[ri], o);
    }
  if ((lane & 3) == 0) {
#pragma unroll
    for (int r = 0; r < 2; r++)
#pragma unroll
      for (int hh = 0; hh < 2; hh++) {
        int rowr = warpM * 32 + r * 16 + (lane >> 2) + hh * 8;
        ((float*)(sm + K1_R1))[warpN * 128 + rowr] = s1p[r * 2 + hh];
        ((float*)(sm + K1_R2))[warpN * 128 + rowr] = s2p[r * 2 + hh];
      }
  }
#pragma unroll
  for (int r = 0; r < 2; r++)
#pragma unroll
    for (int f = 0; f < 8; f++) {
      int row0 = i0 + warpM * 32 + r * 16 + (lane >> 2);
      int col0 = warpN * 64 + f * 8 + 2 * (lane & 3);
#pragma unroll
      for (int hh = 0; hh < 2; hh++) {
        size_t base = (size_t)(row0 + hh * 8) * 256 + col0;
        *(float2*)&g_hf[base] = make_float2(c[r][f][hh * 2], c[r][f][hh * 2 + 1]);
      }
    }
  __syncthreads();
  if (t < 128) {
    const float* r1 = (const float*)(sm + K1_R1);
    const float* r2 = (const float*)(sm + K1_R2);
    float v1 = 0.f, v2 = 0.f;
#pragma unroll
    for (int wn = 0; wn < 4; wn++) { v1 += r1[wn * 128 + t]; v2 += r2[wn * 128 + t]; }
    g_s1[i0 + t] = v1;
    g_s2[i0 + t] = v2;
  }
}

// ============================================================================
// k_rank: rank-by-counting (desc, ties by index), split count.
// ============================================================================
__global__ __launch_bounds__(512) void k_rank() {
  __shared__ float s2sh[2048];
  const int t = threadIdx.x;
  const int seg = blockIdx.x, b = blockIdx.y;
  for (int j = t; j < 2048; j += 512) s2sh[j] = g_s2[b * 2048 + j];
  __syncthreads();
  const int j = seg * 256 + (t >> 1);
  const int half = t & 1;
  const float v = s2sh[j];
  const int k0 = half * 1024;
  int rank = 0;
#pragma unroll 8
  for (int k = k0; k < k0 + 1024; k++) {
    float o = s2sh[k];
    rank += (o > v) || (o == v && k < j);
  }
  rank += __shfl_xor_sync(0xffffffffu, rank, 1);
  if (half == 0) {
    g_perm[b * 2048 + rank] = j;
    g_s2s[b * 2048 + rank] = v;
    g_ep[b * 2048 + rank] = __expf(v);
    g_en[b * 2048 + rank] = __expf(NEG_SLOPE * v);
  }
}

// ============================================================================
// k_prep: fused per-batch scans (dp/dn in smem) + per-row binsearch coefs.
// ============================================================================
__global__ __launch_bounds__(1024) void k_prep() {
  __shared__ float sv[2048];
  __shared__ float sa[2048];
  __shared__ float sdp[2049];
  __shared__ float sdn[2049];
  const int t = threadIdx.x, b = blockIdx.x;

  sv[t] = g_s2s[b * 2048 + t];
  sv[t + 1024] = g_s2s[b * 2048 + t + 1024];
  sa[t] = g_ep[b * 2048 + t];
  sa[t + 1024] = g_ep[b * 2048 + t + 1024];
  __syncthreads();
  for (int off = 1; off < 2048; off <<= 1) {
    float v0 = sa[t] + ((t >= off) ? sa[t - off] : 0.f);
    float v1 = sa[t + 1024] + ((t + 1024 >= off) ? sa[t + 1024 - off] : 0.f);
    __syncthreads();
    sa[t] = v0; sa[t + 1024] = v1;
    __syncthreads();
  }
  if (t == 0) sdp[0] = 0.f;
  sdp[t + 1] = sa[t];
  sdp[t + 1025] = sa[t + 1024];
  __syncthreads();

  sa[t] = g_en[b * 2048 + t];
  sa[t + 1024] = g_en[b * 2048 + t + 1024];
  __syncthreads();
  for (int off = 1; off < 2048; off <<= 1) {
    float v0 = sa[t] + ((t + off < 2048) ? sa[t + off] : 0.f);
    float v1 = sa[t + 1024] + ((t + 1024 + off < 2048) ? sa[t + 1024 + off] : 0.f);
    __syncthreads();
    sa[t] = v0; sa[t + 1024] = v1;
    __syncthreads();
  }
  sdn[t] = sa[t];
  sdn[t + 1024] = sa[t + 1024];
  if (t == 0) sdn[2048] = 0.f;
  __syncthreads();

#pragma unroll
  for (int rr = 0; rr < 2; rr++) {
    const int i = t + rr * 1024;
    const float s1v = g_s1[b * 2048 + i];
    const float tau = -s1v;
    int lo = 0, hi = 2048;
    while (lo < hi) {
      int mid = (lo + hi) >> 1;
      if (sv[mid] > tau) lo = mid + 1; else hi = mid;
    }
    const float up = __expf(s1v);
    const float un = __expf(NEG_SLOPE * s1v);
    const float inv = 1.0f / (up * sdp[lo] + un * sdn[lo]);
    g_kk[b * 2048 + i] = lo;
    g_cu[b * 2048 + i] = inv * up;
    g_cn[b * 2048 + i] = inv * un;
  }
}

// ============================================================================
// k_scanloc: per (32-rank segment, batch): ONE gather pass computing BOTH
// exclusive prefixes P (ep*h) and Q (en*h). grid (64, 8), block 256.
// ============================================================================
__global__ __launch_bounds__(256) void k_scanloc() {
  __shared__ int   sperm[32];
  __shared__ float sep[32], sen[32];
  const int d = threadIdx.x;
  const int s = blockIdx.x, b = blockIdx.y;
  const int k0 = s * 32;

  if (d < 32) {
    sperm[d] = g_perm[b * 2048 + k0 + d];
    sep[d] = g_ep[b * 2048 + k0 + d];
    sen[d] = g_en[b * 2048 + k0 + d];
  }
  __syncthreads();

  float accP = 0.f, accQ = 0.f;
  for (int r0 = 0; r0 < 32; r0 += 8) {
    float vv[8];
#pragma unroll
    for (int q = 0; q < 8; q++)
      vv[q] = g_hf[((size_t)(b * 2048 + sperm[r0 + q])) * 256 + d];
#pragma unroll
    for (int q = 0; q < 8; q++) {
      const size_t o = ((size_t)(b * 2049 + k0 + r0 + q)) * 256 + d;
      g_Pl[o] = accP;
      g_Ql[o] = accQ;
      accP += sep[r0 + q] * vv[q];
      accQ += sen[r0 + q] * vv[q];
    }
  }
  g_segP[(b * 64 + s) * 256 + d] = accP;
  g_segQ[(b * 64 + s) * 256 + d] = accQ;
}

// ============================================================================
// k_segscan: prefix of 64 segment totals (both P and Q). grid 8, block 256.
// ============================================================================
__global__ __launch_bounds__(256) void k_segscan() {
  const int d = threadIdx.x, b = blockIdx.x;
  float accP = 0.f, accQ = 0.f;
  for (int s0 = 0; s0 < 64; s0 += 8) {
    float vP[8], vQ[8];
#pragma unroll
    for (int q = 0; q < 8; q++) {
      vP[q] = g_segP[(b * 64 + s0 + q) * 256 + d];
      vQ[q] = g_segQ[(b * 64 + s0 + q) * 256 + d];
    }
#pragma unroll
    for (int q = 0; q < 8; q++) {
      g_offP[(b * 65 + s0 + q) * 256 + d] = accP;
      g_offQ[(b * 65 + s0 + q) * 256 + d] = accQ;
      accP += vP[q];
      accQ += vQ[q];
    }
  }
  g_offP[(b * 65 + 64) * 256 + d] = accP;   // totals
  g_offQ[(b * 65 + 64) * 256 + d] = accQ;
  g_Pl[((size_t)(b * 2049 + 2048)) * 256 + d] = 0.f;
  g_Ql[((size_t)(b * 2049 + 2048)) * 256 + d] = 0.f;
}

// ============================================================================
// k_out: one block per output row. n = Qtot - Q[k]. grid (2048, 8), block 256.
// ============================================================================
__global__ __launch_bounds__(256) void k_out(float* __restrict__ out) {
  const int d = threadIdx.x;
  const int i = blockIdx.x, b = blockIdx.y;
  const int k = g_kk[b * 2048 + i];
  const float cu = g_cu[b * 2048 + i];
  const float cn = g_cn[b * 2048 + i];
  const int s = (k < 2048) ? (k >> 5) : 64;
  const float p = g_Pl[((size_t)(b * 2049 + k)) * 256 + d] +
                  g_offP[(b * 65 + s) * 256 + d];
  const float q = g_Ql[((size_t)(b * 2049 + k)) * 256 + d] +
                  g_offQ[(b * 65 + s) * 256 + d];
  const float qtot = g_offQ[(b * 65 + 64) * 256 + d];
  float v = cu * p + cn * (qtot - q);
  v = (v > 0.f) ? v : expm1f(v);
  out[((size_t)(b * 2048 + i)) * 256 + d] = v;
}

// ============================================================================
extern "C" void kernel_launch(void* const* d_in, const int* in_sizes, int n_in,
                              void* d_out, int out_size) {
  (void)in_sizes; (void)n_in; (void)out_size;
  const float* x = (const float*)d_in[0];
  const float* W = (const float*)d_in[1];
  const float* a = (const float*)d_in[2];
  float* out = (float*)d_out;

  cudaFuncSetAttribute(k1, cudaFuncAttributeMaxDynamicSharedMemorySize, K1_SMEM);

  k1<<<128, 512, K1_SMEM>>>(x, W, a);
  k_rank<<<dim3(8, B_), 512>>>();
  k_prep<<<B_, 1024>>>();
  k_scanloc<<<dim3(64, B_), 256>>>();
  k_segscan<<<B_, 256>>>();
  k_out<<<dim3(2048, B_), 256>>>(out);
}

// round 14
// speedup vs baseline: 1.1742x; 1.1742x over previous
#include <cuda_runtime.h>
#include <cuda_fp16.h>
#include <cstdint>

// GraphAttentionLayer B=8,T=2048,D=256 — separable-softmax O(T*D) pipeline.
//  k1:       h = x@W^T (SINGLE-TERM fp16 mma — error budget spent here),
//            s1/s2 fp32, h fp32
//  k_rank:   rank-by-counting sort of s2 (desc), split-count, scatter
//  k_prep:   fused per-batch scans (dp/dn in smem) + per-row binsearch coefs
//  k_scanloc:per-64-segment vector scans of ep*h (prefix) / en*h (suffix)
//  k_segscan:segment-total offsets (independent loads, register scan)
//  k_out:    one block per row: gather P/N, combine, ELU

#define B_ 8
#define T_ 2048
#define NEG_SLOPE 0.2f

__device__ float g_hf[B_ * T_ * 256];
__device__ float g_s1[B_ * T_];
__device__ float g_s2[B_ * T_];
__device__ float g_s2s[B_ * T_];
__device__ int   g_perm[B_ * T_];
__device__ float g_ep[B_ * T_];
__device__ float g_en[B_ * T_];
__device__ int   g_kk[B_ * T_];
__device__ float g_cu[B_ * T_];
__device__ float g_cn[B_ * T_];
__device__ float g_Pl[B_ * 2049 * 256];
__device__ float g_Nl[B_ * 2049 * 256];
__device__ float g_segP[B_ * 32 * 256];
__device__ float g_segN[B_ * 32 * 256];
__device__ float g_offP[B_ * 33 * 256];
__device__ float g_offN[B_ * 33 * 256];

// ---------------- helpers ----------------------------------------------------
__device__ __forceinline__ uint32_t smem_u32(const void* p) {
  uint32_t a;
  asm("{ .reg .u64 t; cvta.to.shared.u64 t, %1; cvt.u32.u64 %0, t; }"
      : "=r"(a) : "l"(p));
  return a;
}
__device__ __forceinline__ void ldsm4(uint32_t addr, uint32_t r[4]) {
  asm volatile("ldmatrix.sync.aligned.m8n8.x4.shared.b16 {%0,%1,%2,%3}, [%4];"
               : "=r"(r[0]), "=r"(r[1]), "=r"(r[2]), "=r"(r[3]) : "r"(addr));
}
__device__ __forceinline__ void mma16816(float c[4], const uint32_t a[4],
                                         uint32_t b0, uint32_t b1) {
  asm volatile(
      "mma.sync.aligned.m16n8k16.row.col.f32.f16.f16.f32 "
      "{%0,%1,%2,%3}, {%4,%5,%6,%7}, {%8,%9}, {%0,%1,%2,%3};"
      : "+f"(c[0]), "+f"(c[1]), "+f"(c[2]), "+f"(c[3])
      : "r"(a[0]), "r"(a[1]), "r"(a[2]), "r"(a[3]), "r"(b0), "r"(b1));
}
__device__ __forceinline__ void cpa16(uint32_t dst, const void* src) {
  asm volatile("cp.async.cg.shared.global [%0], [%1], 16;" :: "r"(dst), "l"(src)
               : "memory");
}
#define CP_COMMIT() asm volatile("cp.async.commit_group;" ::: "memory")
#define CP_WAIT(n) asm volatile("cp.async.wait_group %0;" :: "n"(n) : "memory")

// convert 8 fp32 -> fp16x8 packed as uint4
__device__ __forceinline__ uint4 cvt8(const float* v) {
  uint32_t h[4];
#pragma unroll
  for (int q = 0; q < 4; q++) {
    __half2 hv;
    hv.x = __float2half_rn(v[2 * q]);
    hv.y = __float2half_rn(v[2 * q + 1]);
    h[q] = *(uint32_t*)&hv;
  }
  return make_uint4(h[0], h[1], h[2], h[3]);
}

// ============================================================================
// K1: h = x @ W^T, single-term fp16 mma. 128 CTAs, 512 threads, warps 4x4.
// K=256 in 4 chunks of 64. cp.async fp32 staging, overlapped.
// ============================================================================
#define K1_FX 0                    // fp32 x tile [128][68]
#define K1_FW 34816                // fp32 W tile [256][68]
#define K1_AH 104448               // [128][72] fp16
#define K1_BH 122880               // [256][72] fp16
#define K1_AS 159744               // a[512] f32
#define K1_R1 161792               // [4][128] f32
#define K1_R2 163840
#define K1_SMEM 165888

__global__ __launch_bounds__(512, 1) void k1(
    const float* __restrict__ x, const float* __restrict__ W,
    const float* __restrict__ a) {
  extern __shared__ char sm[];
  const uint32_t SB = smem_u32(sm);
  const int t = threadIdx.x, lane = t & 31, wid = t >> 5;
  const int warpM = wid >> 2, warpN = wid & 3;
  const int i0 = blockIdx.x * 128;

#define K1_LOADF32(cc) do {                                                   \
    const int k0_ = (cc) * 64;                                                \
    _Pragma("unroll")                                                         \
    for (int v = 0; v < 4; v++) {                                             \
      int u = v * 512 + t, row = u >> 4, seg = u & 15;                        \
      cpa16(SB + K1_FX + (uint32_t)(row * 68 + seg * 4) * 4,                  \
            &x[(size_t)(i0 + row) * 256 + k0_ + seg * 4]);                    \
    }                                                                         \
    _Pragma("unroll")                                                         \
    for (int v = 0; v < 8; v++) {                                             \
      int u = v * 512 + t, row = u >> 4, seg = u & 15;                        \
      cpa16(SB + K1_FW + (uint32_t)(row * 68 + seg * 4) * 4,                  \
            &W[(size_t)row * 256 + k0_ + seg * 4]);                           \
    }                                                                         \
  } while (0)

  K1_LOADF32(0);
  CP_COMMIT();
  ((float*)(sm + K1_AS))[t] = a[t];

  float c[2][8][4];
#pragma unroll
  for (int r = 0; r < 2; r++)
#pragma unroll
    for (int f = 0; f < 8; f++)
#pragma unroll
      for (int q = 0; q < 4; q++) c[r][f][q] = 0.f;

  CP_WAIT(0);
  __syncthreads();

  for (int ch = 0; ch < 4; ch++) {
    // convert fp32 staging -> fp16 tiles
    {
      const int row = t >> 2, quad = t & 3;
      float v[16];
#pragma unroll
      for (int q = 0; q < 4; q++)
        *(float4*)&v[q * 4] =
            *(const float4*)(sm + K1_FX + (uint32_t)(row * 68 + quad * 16 + q * 4) * 4);
      const uint32_t off = (uint32_t)(row * 72 + quad * 16) * 2;
      *(uint4*)(sm + K1_AH + off) = cvt8(v);
      *(uint4*)(sm + K1_AH + off + 16) = cvt8(v + 8);
    }
    {
      const int row = t >> 1, half = (t & 1) * 32;
      float v[32];
#pragma unroll
      for (int q = 0; q < 8; q++)
        *(float4*)&v[q * 4] =
            *(const float4*)(sm + K1_FW + (uint32_t)(row * 68 + half + q * 4) * 4);
      const uint32_t off = (uint32_t)(row * 72 + half) * 2;
#pragma unroll
      for (int g = 0; g < 4; g++)
        *(uint4*)(sm + K1_BH + off + g * 16) = cvt8(v + g * 8);
    }
    __syncthreads();
    if (ch < 3) { K1_LOADF32(ch + 1); CP_COMMIT(); }

#pragma unroll
    for (int ks = 0; ks < 64; ks += 16) {
      const uint32_t lrow = (uint32_t)(lane & 15);
      const uint32_t lcol = (uint32_t)(ks + ((lane >> 4) << 3));
      uint32_t ah[2][4];
#pragma unroll
      for (int r = 0; r < 2; r++)
        ldsm4(SB + K1_AH + ((warpM * 32 + r * 16 + lrow) * 72 + lcol) * 2, ah[r]);
      uint32_t bh[8][2];
#pragma unroll
      for (int q = 0; q < 4; q++) {
        uint32_t rr[4];
        ldsm4(SB + K1_BH + ((warpN * 64 + q * 16 + lrow) * 72 + lcol) * 2, rr);
        bh[2 * q][0] = rr[0]; bh[2 * q + 1][0] = rr[1];
        bh[2 * q][1] = rr[2]; bh[2 * q + 1][1] = rr[3];
      }
#pragma unroll
      for (int r = 0; r < 2; r++)
#pragma unroll
        for (int f = 0; f < 8; f++) mma16816(c[r][f], ah[r], bh[f][0], bh[f][1]);
    }
    CP_WAIT(0);
    __syncthreads();
  }

  // ---- epilogue: s1/s2 partials + h fp32 stores ----
  const float* as_ = (const float*)(sm + K1_AS);
  float s1p[4], s2p[4];
#pragma unroll
  for (int q = 0; q < 4; q++) { s1p[q] = 0.f; s2p[q] = 0.f; }
#pragma unroll
  for (int r = 0; r < 2; r++)
#pragma unroll
    for (int f = 0; f < 8; f++)
#pragma unroll
      for (int q = 0; q < 4; q++) {
        int col = warpN * 64 + f * 8 + 2 * (lane & 3) + (q & 1);
        int ri = r * 2 + (q >> 1);
        s1p[ri] += c[r][f][q] * as_[col];
        s2p[ri] += c[r][f][q] * as_[256 + col];
      }
#pragma unroll
  for (int o = 1; o < 4; o <<= 1)
#pragma unroll
    for (int ri = 0; ri < 4; ri++) {
      s1p[ri] += __shfl_xor_sync(0xffffffffu, s1p[ri], o);
      s2p[ri] += __shfl_xor_sync(0xffffffffu, s2p[ri], o);
    }
  if ((lane & 3) == 0) {
#pragma unroll
    for (int r = 0; r < 2; r++)
#pragma unroll
      for (int hh = 0; hh < 2; hh++) {
        int rowr = warpM * 32 + r * 16 + (lane >> 2) + hh * 8;
        ((float*)(sm + K1_R1))[warpN * 128 + rowr] = s1p[r * 2 + hh];
        ((float*)(sm + K1_R2))[warpN * 128 + rowr] = s2p[r * 2 + hh];
      }
  }
#pragma unroll
  for (int r = 0; r < 2; r++)
#pragma unroll
    for (int f = 0; f < 8; f++) {
      int row0 = i0 + warpM * 32 + r * 16 + (lane >> 2);
      int col0 = warpN * 64 + f * 8 + 2 * (lane & 3);
#pragma unroll
      for (int hh = 0; hh < 2; hh++) {
        size_t base = (size_t)(row0 + hh * 8) * 256 + col0;
        *(float2*)&g_hf[base] = make_float2(c[r][f][hh * 2], c[r][f][hh * 2 + 1]);
      }
    }
  __syncthreads();
  if (t < 128) {
    const float* r1 = (const float*)(sm + K1_R1);
    const float* r2 = (const float*)(sm + K1_R2);
    float v1 = 0.f, v2 = 0.f;
#pragma unroll
    for (int wn = 0; wn < 4; wn++) { v1 += r1[wn * 128 + t]; v2 += r2[wn * 128 + t]; }
    g_s1[i0 + t] = v1;
    g_s2[i0 + t] = v2;
  }
}

// ============================================================================
// k_rank: rank-by-counting (desc, ties by index), split count.
// ============================================================================
__global__ __launch_bounds__(512) void k_rank() {
  __shared__ float s2sh[2048];
  const int t = threadIdx.x;
  const int seg = blockIdx.x, b = blockIdx.y;
  for (int j = t; j < 2048; j += 512) s2sh[j] = g_s2[b * 2048 + j];
  __syncthreads();
  const int j = seg * 256 + (t >> 1);
  const int half = t & 1;
  const float v = s2sh[j];
  const int k0 = half * 1024;
  int rank = 0;
#pragma unroll 8
  for (int k = k0; k < k0 + 1024; k++) {
    float o = s2sh[k];
    rank += (o > v) || (o == v && k < j);
  }
  rank += __shfl_xor_sync(0xffffffffu, rank, 1);
  if (half == 0) {
    g_perm[b * 2048 + rank] = j;
    g_s2s[b * 2048 + rank] = v;
    g_ep[b * 2048 + rank] = __expf(v);
    g_en[b * 2048 + rank] = __expf(NEG_SLOPE * v);
  }
}

// ============================================================================
// k_prep: fused per-batch scans (dp/dn in smem) + per-row binsearch coefs.
// ============================================================================
__global__ __launch_bounds__(1024) void k_prep() {
  __shared__ float sv[2048];
  __shared__ float sa[2048];
  __shared__ float sdp[2049];
  __shared__ float sdn[2049];
  const int t = threadIdx.x, b = blockIdx.x;

  sv[t] = g_s2s[b * 2048 + t];
  sv[t + 1024] = g_s2s[b * 2048 + t + 1024];
  sa[t] = g_ep[b * 2048 + t];
  sa[t + 1024] = g_ep[b * 2048 + t + 1024];
  __syncthreads();
  for (int off = 1; off < 2048; off <<= 1) {
    float v0 = sa[t] + ((t >= off) ? sa[t - off] : 0.f);
    float v1 = sa[t + 1024] + ((t + 1024 >= off) ? sa[t + 1024 - off] : 0.f);
    __syncthreads();
    sa[t] = v0; sa[t + 1024] = v1;
    __syncthreads();
  }
  if (t == 0) sdp[0] = 0.f;
  sdp[t + 1] = sa[t];
  sdp[t + 1025] = sa[t + 1024];
  __syncthreads();

  sa[t] = g_en[b * 2048 + t];
  sa[t + 1024] = g_en[b * 2048 + t + 1024];
  __syncthreads();
  for (int off = 1; off < 2048; off <<= 1) {
    float v0 = sa[t] + ((t + off < 2048) ? sa[t + off] : 0.f);
    float v1 = sa[t + 1024] + ((t + 1024 + off < 2048) ? sa[t + 1024 + off] : 0.f);
    __syncthreads();
    sa[t] = v0; sa[t + 1024] = v1;
    __syncthreads();
  }
  sdn[t] = sa[t];
  sdn[t + 1024] = sa[t + 1024];
  if (t == 0) sdn[2048] = 0.f;
  __syncthreads();

#pragma unroll
  for (int rr = 0; rr < 2; rr++) {
    const int i = t + rr * 1024;
    const float s1v = g_s1[b * 2048 + i];
    const float tau = -s1v;
    int lo = 0, hi = 2048;
    while (lo < hi) {
      int mid = (lo + hi) >> 1;
      if (sv[mid] > tau) lo = mid + 1; else hi = mid;
    }
    const float up = __expf(s1v);
    const float un = __expf(NEG_SLOPE * s1v);
    const float inv = 1.0f / (up * sdp[lo] + un * sdn[lo]);
    g_kk[b * 2048 + i] = lo;
    g_cu[b * 2048 + i] = inv * up;
    g_cn[b * 2048 + i] = inv * un;
  }
}

// ============================================================================
// k_scanloc: per (64-rank segment, batch): vector scans, chunk-of-8 loads.
// grid (32, 8), block 256.
// ============================================================================
__global__ __launch_bounds__(256) void k_scanloc() {
  __shared__ int   sperm[64];
  __shared__ float sep[64], sen[64];
  const int d = threadIdx.x;
  const int s = blockIdx.x, b = blockIdx.y;
  const int k0 = s * 64;

  if (d < 64) {
    sperm[d] = g_perm[b * 2048 + k0 + d];
    sep[d] = g_ep[b * 2048 + k0 + d];
    sen[d] = g_en[b * 2048 + k0 + d];
  }
  __syncthreads();

  float acc = 0.f;
  for (int r0 = 0; r0 < 64; r0 += 8) {
    float vv[8];
#pragma unroll
    for (int q = 0; q < 8; q++)
      vv[q] = g_hf[((size_t)(b * 2048 + sperm[r0 + q])) * 256 + d];
#pragma unroll
    for (int q = 0; q < 8; q++) {
      g_Pl[((size_t)(b * 2049 + k0 + r0 + q)) * 256 + d] = acc;
      acc += sep[r0 + q] * vv[q];
    }
  }
  g_segP[(b * 32 + s) * 256 + d] = acc;

  acc = 0.f;
  for (int r0 = 56; r0 >= 0; r0 -= 8) {
    float vv[8];
#pragma unroll
    for (int q = 0; q < 8; q++)
      vv[q] = g_hf[((size_t)(b * 2048 + sperm[r0 + q])) * 256 + d];
#pragma unroll
    for (int q = 7; q >= 0; q--) {
      acc += sen[r0 + q] * vv[q];
      g_Nl[((size_t)(b * 2049 + k0 + r0 + q)) * 256 + d] = acc;
    }
  }
  g_segN[(b * 32 + s) * 256 + d] = acc;
}

// ============================================================================
// k_segscan: 32 independent loads -> register scan. grid 8, block 256.
// ============================================================================
__global__ __launch_bounds__(256) void k_segscan() {
  const int d = threadIdx.x, b = blockIdx.x;
  float vP[32], vN[32];
#pragma unroll
  for (int s = 0; s < 32; s++) {
    vP[s] = g_segP[(b * 32 + s) * 256 + d];
    vN[s] = g_segN[(b * 32 + s) * 256 + d];
  }
  float acc = 0.f;
#pragma unroll
  for (int s = 0; s < 32; s++) {
    g_offP[(b * 33 + s) * 256 + d] = acc;
    acc += vP[s];
  }
  g_offP[(b * 33 + 32) * 256 + d] = acc;
  acc = 0.f;
#pragma unroll
  for (int s = 31; s >= 0; s--) {
    g_offN[(b * 33 + s) * 256 + d] = acc;
    acc += vN[s];
  }
  g_offN[(b * 33 + 32) * 256 + d] = 0.f;
  g_Pl[((size_t)(b * 2049 + 2048)) * 256 + d] = 0.f;
  g_Nl[((size_t)(b * 2049 + 2048)) * 256 + d] = 0.f;
}

// ============================================================================
// k_out: one block per output row. grid (2048, 8), block 256.
// ============================================================================
__global__ __launch_bounds__(256) void k_out(float* __restrict__ out) {
  const int d = threadIdx.x;
  const int i = blockIdx.x, b = blockIdx.y;
  const int k = g_kk[b * 2048 + i];
  const float cu = g_cu[b * 2048 + i];
  const float cn = g_cn[b * 2048 + i];
  const int s = k >> 6;
  const float p = g_Pl[((size_t)(b * 2049 + k)) * 256 + d] +
                  g_offP[(b * 33 + s) * 256 + d];
  const float nn = g_Nl[((size_t)(b * 2049 + k)) * 256 + d] +
                   g_offN[(b * 33 + s) * 256 + d];
  float v = cu * p + cn * nn;
  v = (v > 0.f) ? v : expm1f(v);
  out[((size_t)(b * 2048 + i)) * 256 + d] = v;
}

// ============================================================================
extern "C" void kernel_launch(void* const* d_in, const int* in_sizes, int n_in,
                              void* d_out, int out_size) {
  (void)in_sizes; (void)n_in; (void)out_size;
  const float* x = (const float*)d_in[0];
  const float* W = (const float*)d_in[1];
  const float* a = (const float*)d_in[2];
  float* out = (float*)d_out;

  cudaFuncSetAttribute(k1, cudaFuncAttributeMaxDynamicSharedMemorySize, K1_SMEM);

  k1<<<128, 512, K1_SMEM>>>(x, W, a);
  k_rank<<<dim3(8, B_), 512>>>();
  k_prep<<<B_, 1024>>>();
  k_scanloc<<<dim3(32, B_), 256>>>();
  k_segscan<<<B_, 256>>>();
  k_out<<<dim3(2048, B_), 256>>>(out);
}